// round 10
// baseline (speedup 1.0000x reference)
#include <cuda_runtime.h>

// ---------------------------------------------------------------------------
// BiSpikeNet forward. T=8, B=16, F=262144.
//
// Dual-recurrence software pipelining: 128 blocks x 1024 threads; each block
// owns one 16384-elem slice of TWO batches (A=2p, B=2p+1; 16 blocks/batch).
// Per step: waitA -> computeA -> publishA -> waitB -> computeB -> publishB.
// Every barrier has a full compute phase between publish and wait, so spins
// are nearly free and the SM/DRAM pipeline never drains. Membranes for both
// batches live in 128 KiB SMEM. Barrier counters are monotonic across
// launches (graph-replay safe, no reset kernel). Spike bits in registers,
// counts popc'd at the end. Attention MLP: warp0 does batch A, warp1 batch B.
// ---------------------------------------------------------------------------

namespace {
constexpr int T_STEPS  = 8;
constexpr int BATCH    = 16;
constexpr int FDIM     = 1 << 18;            // 262144
constexpr int SLICES   = 16;                 // blocks per batch
constexpr int NBLOCKS  = 128;
constexpr int NTHREADS = 1024;
constexpr int EPS      = FDIM / SLICES;      // 16384 elems per slice
constexpr int KG       = EPS / (NTHREADS*4); // 4 float4 groups/thread
constexpr int F4B      = FDIM / 4;           // 65536 float4 per batch
constexpr int S4       = EPS / 4;            // 4096 float4 per slice
constexpr int NHEADS   = 4;
constexpr int HID      = 64;
constexpr int NBAR     = (T_STEPS + 1) * BATCH;
constexpr int SMEM_DYN = 2 * EPS * 4;        // 128 KiB (two membranes)
}

// Monotonic barrier counters: never reset. Each launch adds exactly 16 per
// counter; a block that saw old=v on its own atomicAdd releases at (v|15)+1.
// Same-stream launches are serialized, so no cross-launch interference.
__device__ unsigned int g_bar[NBAR];
__device__ float        g_abs[T_STEPS][BATCH][SLICES];
__device__ unsigned int g_cnt[BATCH][SLICES][4];

__device__ __forceinline__ void l2_prefetch(const void* p) {
    asm volatile("prefetch.global.L2 [%0];" :: "l"(p));
}

__global__ void __launch_bounds__(NTHREADS, 1) bispike_kernel(
    const float* __restrict__ x,
    const float* __restrict__ decay_p,
    const float* __restrict__ vth_p,
    const float* __restrict__ W1,
    const float* __restrict__ b1,
    const float* __restrict__ W2,
    const float* __restrict__ b2,
    const float* __restrict__ att_w,
    float* __restrict__ out)
{
    extern __shared__ float smem_dyn[];
    float4* s_mA = reinterpret_cast<float4*>(smem_dyn);        // 4096 float4
    float4* s_mB = reinterpret_cast<float4*>(smem_dyn + EPS);  // 4096 float4

    __shared__ float        s_redA[32], s_redB[32];
    __shared__ unsigned int s_redcA[32], s_redcB[32];
    __shared__ float        s_hA[NHEADS*HID], s_hB[NHEADS*HID];
    __shared__ float        s_mapsA[32], s_mapsB[32];
    __shared__ float        s_awA[T_STEPS], s_awB[T_STEPS];
    __shared__ float        s_invA, s_invB;

    const int tid   = threadIdx.x;
    const int lane  = tid & 31;
    const int warp  = tid >> 5;
    const int pair  = blockIdx.x >> 4;       // 0..7
    const int slice = blockIdx.x & 15;       // 0..15
    const int bA    = pair * 2;
    const int bB    = pair * 2 + 1;

    const float d    = 1.0f / (1.0f + expf(-decay_p[0]));
    const float vth  = vth_p[0];
    const float dvth = d * vth;

    unsigned int bitsA[KG], bitsB[KG];
#pragma unroll
    for (int k = 0; k < KG; k++) { bitsA[k] = 0u; bitsB[k] = 0u; }

    const float4* x4 = reinterpret_cast<const float4*>(x);
    const int baseA = bA * F4B + slice * S4;
    const int baseB = bB * F4B + slice * S4;

    float invA = 0.0f, invB = 0.0f;
    unsigned int relA = 0, relB = 0;     // release thresholds (warp0 lane0)

    // ================= temporal LIF loop, A/B interleaved =================
    for (int t = 0; t < T_STEPS; t++) {
        // ---- wait for denom A(t-1) ----
        if (t > 0) {
            if (warp == 0) {
                if (lane == 0) {
                    volatile unsigned int* c = &g_bar[(t-1)*BATCH + bA];
                    while (*c < relA) { }
                }
                __syncwarp();
                float part = (lane < SLICES)
                    ? *(volatile float*)&g_abs[t-1][bA][lane] : 0.0f;
                float tot = 0.0f;
#pragma unroll
                for (int i = 0; i < SLICES; i++)
                    tot += __shfl_sync(0xffffffffu, part, i);
                if (lane == 0)
                    s_invA = 1.0f / (tot * (1.0f/(float)FDIM) + 1e-6f);
            }
            __syncthreads();
            invA = s_invA;
        }
        // ---- compute A(t) ----
        {
            const float4* xp = x4 + (size_t)t * BATCH * F4B + baseA;
            float sa0 = 0.f, sa1 = 0.f, sa2 = 0.f, sa3 = 0.f;
#pragma unroll
            for (int k = 0; k < KG; k++) {
                const int idx = k * NTHREADS + tid;
                float4 xv = xp[idx];
                float xa[4] = {xv.x, xv.y, xv.z, xv.w};
                float ma[4];
                if (t == 0) {
#pragma unroll
                    for (int j = 0; j < 4; j++) ma[j] = xa[j];
                } else {
                    float4 mo = s_mA[idx];
                    float moa[4] = {mo.x, mo.y, mo.z, mo.w};
#pragma unroll
                    for (int j = 0; j < 4; j++) {
                        float mn = moa[j] * invA;
                        bool  sp = (mn >= vth);
                        if (sp) bitsA[k] |= (1u << (8*j + (t-1)));
                        ma[j] = fmaf(d, mn, xa[j]) - (sp ? dvth : 0.0f);
                    }
                }
                s_mA[idx] = make_float4(ma[0], ma[1], ma[2], ma[3]);
                sa0 += fabsf(ma[0]); sa1 += fabsf(ma[1]);
                sa2 += fabsf(ma[2]); sa3 += fabsf(ma[3]);
            }
            float sum = (sa0 + sa1) + (sa2 + sa3);
            if (t + 1 < T_STEPS && (lane & 7) == 0) {
                const float4* xn = x4 + (size_t)(t+1) * BATCH * F4B + baseA;
#pragma unroll
                for (int k = 0; k < KG; k++)
                    l2_prefetch(&xn[k * NTHREADS + tid]);
            }
#pragma unroll
            for (int off = 16; off > 0; off >>= 1)
                sum += __shfl_xor_sync(0xffffffffu, sum, off);
            if (lane == 0) s_redA[warp] = sum;
            __syncthreads();
            if (warp == 0) {
                float v = s_redA[lane];
#pragma unroll
                for (int off = 16; off > 0; off >>= 1)
                    v += __shfl_xor_sync(0xffffffffu, v, off);
                if (lane == 0) {
                    *(volatile float*)&g_abs[t][bA][slice] = v;
                    __threadfence();
                    unsigned int old = atomicAdd(&g_bar[t*BATCH + bA], 1u);
                    relA = (old | 15u) + 1u;
                }
            }
        }
        // ---- wait for denom B(t-1) ----
        if (t > 0) {
            if (warp == 0) {
                if (lane == 0) {
                    volatile unsigned int* c = &g_bar[(t-1)*BATCH + bB];
                    while (*c < relB) { }
                }
                __syncwarp();
                float part = (lane < SLICES)
                    ? *(volatile float*)&g_abs[t-1][bB][lane] : 0.0f;
                float tot = 0.0f;
#pragma unroll
                for (int i = 0; i < SLICES; i++)
                    tot += __shfl_sync(0xffffffffu, part, i);
                if (lane == 0)
                    s_invB = 1.0f / (tot * (1.0f/(float)FDIM) + 1e-6f);
            }
            __syncthreads();
            invB = s_invB;
        }
        // ---- compute B(t) ----
        {
            const float4* xp = x4 + (size_t)t * BATCH * F4B + baseB;
            float sa0 = 0.f, sa1 = 0.f, sa2 = 0.f, sa3 = 0.f;
#pragma unroll
            for (int k = 0; k < KG; k++) {
                const int idx = k * NTHREADS + tid;
                float4 xv = xp[idx];
                float xa[4] = {xv.x, xv.y, xv.z, xv.w};
                float ma[4];
                if (t == 0) {
#pragma unroll
                    for (int j = 0; j < 4; j++) ma[j] = xa[j];
                } else {
                    float4 mo = s_mB[idx];
                    float moa[4] = {mo.x, mo.y, mo.z, mo.w};
#pragma unroll
                    for (int j = 0; j < 4; j++) {
                        float mn = moa[j] * invB;
                        bool  sp = (mn >= vth);
                        if (sp) bitsB[k] |= (1u << (8*j + (t-1)));
                        ma[j] = fmaf(d, mn, xa[j]) - (sp ? dvth : 0.0f);
                    }
                }
                s_mB[idx] = make_float4(ma[0], ma[1], ma[2], ma[3]);
                sa0 += fabsf(ma[0]); sa1 += fabsf(ma[1]);
                sa2 += fabsf(ma[2]); sa3 += fabsf(ma[3]);
            }
            float sum = (sa0 + sa1) + (sa2 + sa3);
            if (t + 1 < T_STEPS && (lane & 7) == 0) {
                const float4* xn = x4 + (size_t)(t+1) * BATCH * F4B + baseB;
#pragma unroll
                for (int k = 0; k < KG; k++)
                    l2_prefetch(&xn[k * NTHREADS + tid]);
            }
#pragma unroll
            for (int off = 16; off > 0; off >>= 1)
                sum += __shfl_xor_sync(0xffffffffu, sum, off);
            if (lane == 0) s_redB[warp] = sum;
            __syncthreads();
            if (warp == 0) {
                float v = s_redB[lane];
#pragma unroll
                for (int off = 16; off > 0; off >>= 1)
                    v += __shfl_xor_sync(0xffffffffu, v, off);
                if (lane == 0) {
                    *(volatile float*)&g_abs[t][bB][slice] = v;
                    __threadfence();
                    unsigned int old = atomicAdd(&g_bar[t*BATCH + bB], 1u);
                    relB = (old | 15u) + 1u;
                }
            }
        }
    }

    // ================= final denominators (t = T-1) =================
    if (warp == 0) {
        if (lane == 0) {
            volatile unsigned int* c = &g_bar[(T_STEPS-1)*BATCH + bA];
            while (*c < relA) { }
        }
        __syncwarp();
        float part = (lane < SLICES)
            ? *(volatile float*)&g_abs[T_STEPS-1][bA][lane] : 0.0f;
        float tot = 0.0f;
#pragma unroll
        for (int i = 0; i < SLICES; i++)
            tot += __shfl_sync(0xffffffffu, part, i);
        if (lane == 0)
            s_invA = 1.0f / (tot * (1.0f/(float)FDIM) + 1e-6f);

        if (lane == 0) {
            volatile unsigned int* c = &g_bar[(T_STEPS-1)*BATCH + bB];
            while (*c < relB) { }
        }
        __syncwarp();
        part = (lane < SLICES)
            ? *(volatile float*)&g_abs[T_STEPS-1][bB][lane] : 0.0f;
        tot = 0.0f;
#pragma unroll
        for (int i = 0; i < SLICES; i++)
            tot += __shfl_sync(0xffffffffu, part, i);
        if (lane == 0)
            s_invB = 1.0f / (tot * (1.0f/(float)FDIM) + 1e-6f);
    }
    __syncthreads();
    invA = s_invA;
    invB = s_invB;

    // ================= final spikes =================
#pragma unroll
    for (int k = 0; k < KG; k++) {
        const int idx = k * NTHREADS + tid;
        float4 moA = s_mA[idx];
        float4 moB = s_mB[idx];
        float a4[4] = {moA.x, moA.y, moA.z, moA.w};
        float b4[4] = {moB.x, moB.y, moB.z, moB.w};
#pragma unroll
        for (int j = 0; j < 4; j++) {
            if (a4[j] * invA >= vth) bitsA[k] |= (1u << (8*j + 7));
            if (b4[j] * invB >= vth) bitsB[k] |= (1u << (8*j + 7));
        }
    }

    // ================= spike counts (popc, packed 2x16) =================
    {
#pragma unroll
        for (int q = 0; q < 4; q++) {
            unsigned int m_lo = 0x01010101u << (2*q);
            unsigned int m_hi = 0x01010101u << (2*q + 1);
            unsigned int aLo = 0, aHi = 0, bLo = 0, bHi = 0;
#pragma unroll
            for (int k = 0; k < KG; k++) {
                aLo += __popc(bitsA[k] & m_lo);
                aHi += __popc(bitsA[k] & m_hi);
                bLo += __popc(bitsB[k] & m_lo);
                bHi += __popc(bitsB[k] & m_hi);
            }
            unsigned int vA = aLo | (aHi << 16);   // slice count <= 16384: fits
            unsigned int vB = bLo | (bHi << 16);
#pragma unroll
            for (int off = 16; off > 0; off >>= 1) {
                vA += __shfl_xor_sync(0xffffffffu, vA, off);
                vB += __shfl_xor_sync(0xffffffffu, vB, off);
            }
            if (lane == 0) { s_redcA[warp] = vA; s_redcB[warp] = vB; }
            __syncthreads();
            if (warp == 0) {
                unsigned int cA = s_redcA[lane];
                unsigned int cB = s_redcB[lane];
#pragma unroll
                for (int off = 16; off > 0; off >>= 1) {
                    cA += __shfl_xor_sync(0xffffffffu, cA, off);
                    cB += __shfl_xor_sync(0xffffffffu, cB, off);
                }
                if (lane == 0) {
                    *(volatile unsigned int*)&g_cnt[bA][slice][q] = cA;
                    *(volatile unsigned int*)&g_cnt[bB][slice][q] = cB;
                }
            }
            __syncthreads();
        }
        if (warp == 0 && lane == 0) {
            __threadfence();
            unsigned int oA = atomicAdd(&g_bar[T_STEPS*BATCH + bA], 1u);
            unsigned int oB = atomicAdd(&g_bar[T_STEPS*BATCH + bB], 1u);
            unsigned int rA = (oA | 15u) + 1u;
            unsigned int rB = (oB | 15u) + 1u;
            volatile unsigned int* cA = &g_bar[T_STEPS*BATCH + bA];
            volatile unsigned int* cB = &g_bar[T_STEPS*BATCH + bB];
            while (*cA < rA) { }
            while (*cB < rB) { }
        }
        __syncthreads();
    }

    // ================= attention MLP: warp0 -> A, warp1 -> B ==============
    if (warp < 2) {
        const int  bb    = warp ? bB : bA;
        float*     sh    = warp ? s_hB : s_hA;
        float*     smaps = warp ? s_mapsB : s_mapsA;
        float*     saw   = warp ? s_awB : s_awA;

        float summ[T_STEPS];
#pragma unroll
        for (int q = 0; q < 4; q++) {
            unsigned int lo = 0, hi = 0;
            if (lane < SLICES) {
                unsigned int v = *(volatile unsigned int*)&g_cnt[bb][lane][q];
                lo = v & 0xffffu;                  // unpack BEFORE cross-slice sum
                hi = v >> 16;
            }
#pragma unroll
            for (int off = 16; off > 0; off >>= 1) {
                lo += __shfl_xor_sync(0xffffffffu, lo, off);
                hi += __shfl_xor_sync(0xffffffffu, hi, off);
            }
            summ[2*q]     = (float)lo * (1.0f/(float)FDIM);
            summ[2*q + 1] = (float)hi * (1.0f/(float)FDIM);
        }
#pragma unroll
        for (int r = 0; r < 8; r++) {
            int idx = r * 32 + lane;
            float acc = b1[idx];
#pragma unroll
            for (int t = 0; t < T_STEPS; t++)
                acc += summ[t] * W1[idx * T_STEPS + t];
            sh[idx] = fmaxf(acc, 0.0f);
        }
        __syncwarp();
        {
            float acc = b2[lane];
            const int hb = (lane >> 3) * HID;
            const float* w2p = W2 + lane * HID;
#pragma unroll
            for (int hd = 0; hd < HID; hd++)
                acc += sh[hb + hd] * w2p[hd];
            smaps[lane] = acc * att_w[lane >> 3];
        }
        __syncwarp();
        if (lane == 0) {
            float w[T_STEPS];
            float mx = -1e30f;
#pragma unroll
            for (int t = 0; t < T_STEPS; t++) {
                w[t] = smaps[t] + smaps[8+t] + smaps[16+t] + smaps[24+t];
                mx = fmaxf(mx, w[t]);
            }
            float ssum = 0.0f;
#pragma unroll
            for (int t = 0; t < T_STEPS; t++) { w[t] = expf(w[t] - mx); ssum += w[t]; }
            float invs = 1.0f / ssum;
#pragma unroll
            for (int t = 0; t < T_STEPS; t++) saw[t] = w[t] * invs;
        }
    }
    __syncthreads();

    float awA[T_STEPS], awB[T_STEPS];
#pragma unroll
    for (int t = 0; t < T_STEPS; t++) { awA[t] = s_awA[t]; awB[t] = s_awB[t]; }

    // ================= outputs for both slices =================
    float4* o4 = reinterpret_cast<float4*>(out);
#pragma unroll
    for (int k = 0; k < KG; k++) {
        unsigned int btA = bitsA[k];
        unsigned int btB = bitsB[k];
        float oA[4], oB[4];
#pragma unroll
        for (int j = 0; j < 4; j++) {
            float vA = 0.0f, vB = 0.0f;
#pragma unroll
            for (int t = 0; t < T_STEPS; t++) {
                vA += ((btA >> (8*j + t)) & 1u) ? awA[t] : 0.0f;
                vB += ((btB >> (8*j + t)) & 1u) ? awB[t] : 0.0f;
            }
            oA[j] = vA; oB[j] = vB;
        }
        o4[baseA + k * NTHREADS + tid] = make_float4(oA[0], oA[1], oA[2], oA[3]);
        o4[baseB + k * NTHREADS + tid] = make_float4(oB[0], oB[1], oB[2], oB[3]);
    }
}

extern "C" void kernel_launch(void* const* d_in, const int* in_sizes, int n_in,
                              void* d_out, int out_size) {
    (void)in_sizes; (void)n_in; (void)out_size;
    cudaFuncSetAttribute(bispike_kernel,
                         cudaFuncAttributeMaxDynamicSharedMemorySize, SMEM_DYN);
    bispike_kernel<<<NBLOCKS, NTHREADS, SMEM_DYN>>>(
        (const float*)d_in[0],   // x
        (const float*)d_in[1],   // decay_param
        (const float*)d_in[2],   // v_th
        (const float*)d_in[3],   // W1
        (const float*)d_in[4],   // b1
        (const float*)d_in[5],   // W2
        (const float*)d_in[6],   // b2
        (const float*)d_in[7],   // att_w
        (float*)d_out);
}

// round 11
// speedup vs baseline: 1.3859x; 1.3859x over previous
#include <cuda_runtime.h>

// ---------------------------------------------------------------------------
// BiSpikeNet forward, single persistent kernel. T=8, B=16, F=C*H*W=262144.
//
// EXACT round-2 winner (55.3us) with ONE isolated change: spike-count
// accumulation is removed from the per-step critical path (no cnt shuffle
// tree per step); counts are recovered at the end via popc on the
// register-resident spike bits. Denominator arithmetic is untouched ->
// output bit-identical to R2.
//
// 128 blocks (16 batches x 8 blocks/batch), 1024 threads. Membrane state in
// SMEM (128 KiB), packed spike bits in registers. Per-batch software barrier
// (counters reset by a prologue kernel each launch -> graph-replay safe).
// While waiting at the barrier we prefetch x[t+1] into L2.
// ---------------------------------------------------------------------------

namespace {
constexpr int T_STEPS        = 8;
constexpr int BATCH          = 16;
constexpr int FDIM           = 1 << 18;          // 262144
constexpr int BLKS_PER_BATCH = 8;
constexpr int NBLOCKS        = BATCH * BLKS_PER_BATCH;   // 128
constexpr int NTHREADS       = 1024;
constexpr int EPB            = FDIM / BLKS_PER_BATCH;    // 32768 elems/block
constexpr int KG             = EPB / (NTHREADS * 4);     // 8 float4 groups/thread
constexpr int NHEADS         = 4;
constexpr int HID            = 64;
constexpr int NBAR           = (T_STEPS + 1) * BATCH;    // 144 counters
}

__device__ unsigned int g_bar[NBAR];
__device__ float g_abs_part[T_STEPS][BATCH][BLKS_PER_BATCH];
__device__ unsigned int g_cnt_part[BATCH][BLKS_PER_BATCH][4];

__global__ void reset_kernel() {
    if (threadIdx.x < NBAR) g_bar[threadIdx.x] = 0u;
}

__device__ __forceinline__ void l2_prefetch(const void* p) {
    asm volatile("prefetch.global.L2 [%0];" :: "l"(p));
}

__global__ void __launch_bounds__(NTHREADS, 1) bispike_kernel(
    const float* __restrict__ x,
    const float* __restrict__ decay_p,
    const float* __restrict__ vth_p,
    const float* __restrict__ W1,
    const float* __restrict__ b1,
    const float* __restrict__ W2,
    const float* __restrict__ b2,
    const float* __restrict__ att_w,
    float* __restrict__ out)
{
    extern __shared__ float s_m[];               // EPB floats: membrane state
    __shared__ float s_red[32];
    __shared__ unsigned int s_redc[32];
    __shared__ float s_h[NHEADS * HID];
    __shared__ float s_maps[32];
    __shared__ float s_aw[T_STEPS];
    __shared__ float s_invd;

    const int tid  = threadIdx.x;
    const int lane = tid & 31;
    const int warp = tid >> 5;
    const int b    = blockIdx.x >> 3;            // batch
    const int blk  = blockIdx.x & 7;             // slice within batch
    const int f0   = blk * EPB;

    const float d   = 1.0f / (1.0f + expf(-decay_p[0]));
    const float vth = vth_p[0];

    unsigned int bits4[KG];                      // 4 elements x 8 step-bits per word
#pragma unroll
    for (int k = 0; k < KG; k++) bits4[k] = 0u;

    float4* s_m4 = reinterpret_cast<float4*>(s_m);
    float inv_prev = 0.0f;

    const float* xbase = x + (size_t)b * FDIM + f0;

    // ---------------- temporal LIF loop ----------------
    for (int t = 0; t < T_STEPS; t++) {
        const float4* xp = reinterpret_cast<const float4*>(
            xbase + (size_t)t * BATCH * FDIM);
        float sa0 = 0.0f, sa1 = 0.0f, sa2 = 0.0f, sa3 = 0.0f;
#pragma unroll
        for (int k = 0; k < KG; k++) {
            const int idx4 = k * NTHREADS + tid;
            float4 xv = xp[idx4];
            float xa[4] = {xv.x, xv.y, xv.z, xv.w};
            float ma[4];
            if (t == 0) {
#pragma unroll
                for (int j = 0; j < 4; j++) ma[j] = xa[j];
            } else {
                float4 mo = s_m4[idx4];
                float moa[4] = {mo.x, mo.y, mo.z, mo.w};
#pragma unroll
                for (int j = 0; j < 4; j++) {
                    float mn = moa[j] * inv_prev;   // normalized m_{t-1}
                    bool  sp = (mn >= vth);
                    float sf = sp ? 1.0f : 0.0f;
                    if (sp) bits4[k] |= (1u << (8 * j + (t - 1)));
                    ma[j] = d * (mn - vth * sf) + xa[j];
                }
            }
            s_m4[idx4] = make_float4(ma[0], ma[1], ma[2], ma[3]);
            sa0 += fabsf(ma[0]); sa1 += fabsf(ma[1]);
            sa2 += fabsf(ma[2]); sa3 += fabsf(ma[3]);
        }
        float sum_abs = (sa0 + sa1) + (sa2 + sa3);

        // L2 prefetch of x[t+1] while we reduce + wait at the barrier.
        // One prefetch per 128B line: lanes 0,8,16,24 cover the warp's span.
        if (t + 1 < T_STEPS && (lane & 7) == 0) {
            const float4* xn = reinterpret_cast<const float4*>(
                xbase + (size_t)(t + 1) * BATCH * FDIM);
#pragma unroll
            for (int k = 0; k < KG; k++)
                l2_prefetch(&xn[k * NTHREADS + tid]);
        }

        // deterministic block reduction (|m| sum only -- counts moved out)
#pragma unroll
        for (int off = 16; off > 0; off >>= 1)
            sum_abs += __shfl_xor_sync(0xffffffffu, sum_abs, off);
        if (lane == 0) s_red[warp] = sum_abs;
        __syncthreads();
        if (warp == 0) {
            float v = s_red[lane];
#pragma unroll
            for (int off = 16; off > 0; off >>= 1)
                v += __shfl_xor_sync(0xffffffffu, v, off);
            if (lane == 0) {
                *(volatile float*)&g_abs_part[t][b][blk] = v;
                __threadfence();
                unsigned int* bar = &g_bar[t * BATCH + b];
                atomicAdd(bar, 1u);
                volatile unsigned int* ctr = bar;
                while (*ctr < (unsigned)BLKS_PER_BATCH) { }
                // deterministic 8-partial sum for this batch (same as R2)
                volatile float* pp = &g_abs_part[t][b][0];
                float tot = 0.0f;
#pragma unroll
                for (int i = 0; i < BLKS_PER_BATCH; i++) tot += pp[i];
                float denom = tot * (1.0f / (float)FDIM) + 1e-6f;
                s_invd = 1.0f / denom;
            }
        }
        __syncthreads();
        inv_prev = s_invd;
    }

    // ---------------- final step spikes (t = T-1) ----------------
    {
#pragma unroll
        for (int k = 0; k < KG; k++) {
            const int idx4 = k * NTHREADS + tid;
            float4 mo = s_m4[idx4];
            float moa[4] = {mo.x, mo.y, mo.z, mo.w};
#pragma unroll
            for (int j = 0; j < 4; j++) {
                if (moa[j] * inv_prev >= vth)
                    bits4[k] |= (1u << (8 * j + 7));
            }
        }
    }

    // ---------------- spike counts via popc (packed 2x16-bit) -------------
    {
        unsigned int packed[4];
#pragma unroll
        for (int q = 0; q < 4; q++) {
            unsigned int c_lo = 0, c_hi = 0;
            unsigned int m_lo = 0x01010101u << (2 * q);
            unsigned int m_hi = 0x01010101u << (2 * q + 1);
#pragma unroll
            for (int k = 0; k < KG; k++) {
                c_lo += __popc(bits4[k] & m_lo);
                c_hi += __popc(bits4[k] & m_hi);
            }
            packed[q] = c_lo | (c_hi << 16);     // block count <= 32768: fits
        }
#pragma unroll
        for (int q = 0; q < 4; q++) {
            unsigned int v = packed[q];
#pragma unroll
            for (int off = 16; off > 0; off >>= 1)
                v += __shfl_xor_sync(0xffffffffu, v, off);
            if (lane == 0) s_redc[warp] = v;
            __syncthreads();
            if (warp == 0) {
                unsigned int c = s_redc[lane];
#pragma unroll
                for (int off = 16; off > 0; off >>= 1)
                    c += __shfl_xor_sync(0xffffffffu, c, off);
                if (lane == 0)
                    *(volatile unsigned int*)&g_cnt_part[b][blk][q] = c;
            }
            __syncthreads();
        }
        if (warp == 0 && lane == 0) {
            __threadfence();
            unsigned int* bar = &g_bar[T_STEPS * BATCH + b];
            atomicAdd(bar, 1u);
            volatile unsigned int* ctr = bar;
            while (*ctr < (unsigned)BLKS_PER_BATCH) { }
        }
        __syncthreads();
    }

    // ---------------- tiny attention MLP (warp 0, per batch) ----------------
    if (warp == 0) {
        float summ[T_STEPS];
#pragma unroll
        for (int q = 0; q < 4; q++) {
            unsigned int lo = 0, hi = 0;
            if (lane < BLKS_PER_BATCH) {
                unsigned int v = *(volatile unsigned int*)&g_cnt_part[b][lane][q];
                lo = v & 0xffffu;                 // unpack BEFORE cross-block sum
                hi = v >> 16;
            }
#pragma unroll
            for (int off = 16; off > 0; off >>= 1) {   // uniform, full-warp
                lo += __shfl_xor_sync(0xffffffffu, lo, off);
                hi += __shfl_xor_sync(0xffffffffu, hi, off);
            }
            summ[2 * q]     = (float)lo * (1.0f / (float)FDIM);
            summ[2 * q + 1] = (float)hi * (1.0f / (float)FDIM);
        }
        // h[n,hd] = relu(sum_t summ[t]*W1[n,hd,t] + b1[n,hd]); 256 vals, 8/lane
#pragma unroll
        for (int r = 0; r < 8; r++) {
            int idx = r * 32 + lane;
            float acc = b1[idx];
#pragma unroll
            for (int t = 0; t < T_STEPS; t++)
                acc += summ[t] * W1[idx * T_STEPS + t];
            s_h[idx] = fmaxf(acc, 0.0f);
        }
        __syncwarp();
        // maps[n,t] = sum_hd h[n,hd]*W2[n,t,hd] + b2[n,t];  lane = n*8+t
        {
            float acc = b2[lane];
            const int hb = (lane >> 3) * HID;
            const float* w2p = W2 + lane * HID;
#pragma unroll
            for (int hd = 0; hd < HID; hd++)
                acc += s_h[hb + hd] * w2p[hd];
            s_maps[lane] = acc * att_w[lane >> 3];
        }
        __syncwarp();
        if (lane == 0) {
            float w[T_STEPS];
            float mx = -1e30f;
#pragma unroll
            for (int t = 0; t < T_STEPS; t++) {
                w[t] = s_maps[t] + s_maps[8 + t] + s_maps[16 + t] + s_maps[24 + t];
                mx = fmaxf(mx, w[t]);
            }
            float ssum = 0.0f;
#pragma unroll
            for (int t = 0; t < T_STEPS; t++) { w[t] = expf(w[t] - mx); ssum += w[t]; }
            float inv = 1.0f / ssum;
#pragma unroll
            for (int t = 0; t < T_STEPS; t++) s_aw[t] = w[t] * inv;
        }
    }
    __syncthreads();

    float aw[T_STEPS];
#pragma unroll
    for (int t = 0; t < T_STEPS; t++) aw[t] = s_aw[t];

    // ---------------- output: out[b,f] = sum_t aw[t] * spike(t,f) ----------
    float4* op = reinterpret_cast<float4*>(out + (size_t)b * FDIM + f0);
#pragma unroll
    for (int k = 0; k < KG; k++) {
        unsigned int bt = bits4[k];
        float o[4];
#pragma unroll
        for (int j = 0; j < 4; j++) {
            float v = 0.0f;
#pragma unroll
            for (int t = 0; t < T_STEPS; t++)
                v += ((bt >> (8 * j + t)) & 1u) ? aw[t] : 0.0f;
            o[j] = v;
        }
        op[k * NTHREADS + tid] = make_float4(o[0], o[1], o[2], o[3]);
    }
}

extern "C" void kernel_launch(void* const* d_in, const int* in_sizes, int n_in,
                              void* d_out, int out_size) {
    (void)in_sizes; (void)n_in; (void)out_size;
    cudaFuncSetAttribute(bispike_kernel,
                         cudaFuncAttributeMaxDynamicSharedMemorySize,
                         EPB * (int)sizeof(float));
    reset_kernel<<<1, 256>>>();
    bispike_kernel<<<NBLOCKS, NTHREADS, EPB * sizeof(float)>>>(
        (const float*)d_in[0],   // x
        (const float*)d_in[1],   // decay_param
        (const float*)d_in[2],   // v_th
        (const float*)d_in[3],   // W1
        (const float*)d_in[4],   // b1
        (const float*)d_in[5],   // W2
        (const float*)d_in[6],   // b2
        (const float*)d_in[7],   // att_w
        (float*)d_out);
}